// round 2
// baseline (speedup 1.0000x reference)
#include <cuda_runtime.h>
#include <cstdint>

// Problem constants
// B=4, P2=64, TOPK=16, W2=49, C_KV=512
// r_idx: (B, P2, TOPK)  -- declared int64 in reference, but JAX x64-disabled
//        silently emits int32; read as int32.
// kv:    float32 (B, P2, W2, C_KV)
// out:   float32 (B, P2, TOPK, W2, C_KV)

#define B_    4
#define P2_   64
#define TOPK_ 16
#define W2_   49
#define CKV_  512

// Region = W2*CKV = 25088 floats = 6272 float4 = 49 blocks * 128 threads.

__global__ void __launch_bounds__(128, 16) kv_gather_kernel(
    const int*    __restrict__ r_idx,
    const float4* __restrict__ kv,
    float4*       __restrict__ out)
{
    const int region = blockIdx.y;              // 0..4095 = (b, p, k) flattened
    const int b = region >> 10;                 // region / (P2*TOPK)

    int r = __ldg(&r_idx[region]);
    // memory-safety clamp: guarantees no OOB even if dtype guess is wrong,
    // converting a crash into a measurable rel_err signal.
    r = min(max(r, 0), P2_ - 1);

    const int REGION_F4 = (W2_ * CKV_) / 4;     // 6272

    const long long src_base = ((long long)(b * P2_ + r)) * REGION_F4;
    const long long dst_base = (long long)region * REGION_F4;

    const int off = blockIdx.x * 128 + threadIdx.x;   // 0..6271

    float4 v = __ldg(&kv[src_base + off]);
    // evict-first streaming store: keep the 25.7MB kv working set L2-resident
    // against the 411MB write stream
    __stcs(&out[dst_base + off], v);
}

extern "C" void kernel_launch(void* const* d_in, const int* in_sizes, int n_in,
                              void* d_out, int out_size)
{
    const int*    r_idx = (const int*)d_in[0];
    const float4* kv    = (const float4*)d_in[1];
    float4*       out   = (float4*)d_out;

    dim3 grid(49, B_ * P2_ * TOPK_);   // (49, 4096)
    kv_gather_kernel<<<grid, 128>>>(r_idx, kv, out);
}

// round 3
// speedup vs baseline: 1.6929x; 1.6929x over previous
#include <cuda_runtime.h>
#include <cstdint>

// B=4, P2=64, TOPK=16, W2=49, C_KV=512
// r_idx: int32 (B, P2, TOPK) [reference says int64 but JAX x64-off emits int32]
// kv:    float32 (B, P2, W2, C_KV)
// out:   float32 (B, P2, TOPK, W2, C_KV)
//
// Region = W2*CKV = 25088 floats = 6272 float4.
// 6272 = 448 threads * 14 float4/thread. One block per region (4096 blocks).
// Load-all-then-store-all gives 14 independent LDG.128 in flight per thread.

#define B_    4
#define P2_   64
#define TOPK_ 16
#define W2_   49
#define CKV_  512

#define THREADS_   448
#define PER_THREAD_ 14
#define REGION_F4  ((W2_ * CKV_) / 4)   // 6272

__global__ void __launch_bounds__(THREADS_, 2) kv_gather_kernel(
    const int*    __restrict__ r_idx,
    const float4* __restrict__ kv,
    float4*       __restrict__ out)
{
    const int region = blockIdx.x;              // 0..4095 = (b, p, k) flattened
    const int b = region >> 10;                 // region / (P2*TOPK)

    int r = __ldg(&r_idx[region]);
    r = min(max(r, 0), P2_ - 1);                // safety clamp (free, ALU-idle kernel)

    const float4* __restrict__ src = kv  + (long long)(b * P2_ + r) * REGION_F4;
    float4*       __restrict__ dst = out + (long long)region * REGION_F4;

    const int t = threadIdx.x;

    float4 v[PER_THREAD_];
#pragma unroll
    for (int i = 0; i < PER_THREAD_; i++)
        v[i] = __ldg(&src[t + i * THREADS_]);

#pragma unroll
    for (int i = 0; i < PER_THREAD_; i++)
        __stcs(&dst[t + i * THREADS_], v[i]);
}

extern "C" void kernel_launch(void* const* d_in, const int* in_sizes, int n_in,
                              void* d_out, int out_size)
{
    const int*    r_idx = (const int*)d_in[0];
    const float4* kv    = (const float4*)d_in[1];
    float4*       out   = (float4*)d_out;

    kv_gather_kernel<<<B_ * P2_ * TOPK_, THREADS_>>>(r_idx, kv, out);
}